// round 3
// baseline (speedup 1.0000x reference)
#include <cuda_runtime.h>
#include <math.h>
#include <limits.h>

// Problem constants (fixed by the reference setup_inputs)
#define BB    4
#define NN    8192
#define MM    8192
#define TPB   256
#define QPT   2                       // queries per thread
#define QBLK  (TPB * QPT)             // 512 queries per block
#define SPLIT 16
#define CH    (MM / SPLIT)            // 512 context points per chunk
#define QB    (NN / QBLK)             // 16 query-blocks per batch

// Output layout: [unit BB*3*NN][cen BB*3*NN][pos BB*NN]
#define OFF_U 0
#define OFF_C (BB * 3 * NN)
#define OFF_P (2 * BB * 3 * NN)

// Scratch (allocation-free: __device__ globals)
__device__ float g_pd[3 * SPLIT * BB * NN];
__device__ int   g_pi[3 * SPLIT * BB * NN];
__device__ unsigned char g_mask[BB * NN];
__device__ int g_first[BB];

#define PD(k, s, q) g_pd[(((k) * SPLIT + (s)) * (BB * NN)) + (q)]
#define PI(k, s, q) g_pi[(((k) * SPLIT + (s)) * (BB * NN)) + (q)]

// Stable top-3 insert (strict '<' => lowest-index-first ties, matches lax.top_k)
#define INS(D0, D1, D2, I0, I1, I2, d, jj)                                   \
    if ((d) < D2) {                                                          \
        if ((d) < D0)      { D2 = D1; I2 = I1; D1 = D0; I1 = I0;             \
                             D0 = (d); I0 = (jj); }                          \
        else if ((d) < D1) { D2 = D1; I2 = I1; D1 = (d); I1 = (jj); }        \
        else               { D2 = (d); I2 = (jj); }                          \
    }

__global__ void __launch_bounds__(TPB)
surf_scan_kernel(const float* __restrict__ center,
                 const float* __restrict__ context)
{
    __shared__ float4 sctx[CH];   // 8 KB

    // blockIdx.x = ((b * QB) + qb) * SPLIT + s
    const int s  = blockIdx.x % SPLIT;
    const int r  = blockIdx.x / SPLIT;
    const int qb = r % QB;
    const int b  = r / QB;
    const int j0 = s * CH;

    // Cooperative load of this chunk as (x, y, z, |p|^2)
    const float* ctx = context + (size_t)b * 3 * MM;
    #pragma unroll
    for (int j = threadIdx.x; j < CH; j += TPB) {
        float x = ctx[j0 + j];
        float y = ctx[MM + j0 + j];
        float z = ctx[2 * MM + j0 + j];
        sctx[j] = make_float4(x, y, z, x * x + y * y + z * z);
    }
    __syncthreads();

    // Two query points per thread: n and n + TPB within this 512-query block
    const int nA = qb * QBLK + threadIdx.x;
    const int nB = nA + TPB;
    const float* cenp = center + (size_t)b * 3 * NN;
    const float qxA = cenp[nA],          qxB = cenp[nB];
    const float qyA = cenp[NN + nA],     qyB = cenp[NN + nB];
    const float qzA = cenp[2 * NN + nA], qzB = cenp[2 * NN + nB];
    const float cnA = qxA * qxA + qyA * qyA + qzA * qzA;
    const float cnB = qxB * qxB + qyB * qyB + qzB * qzB;

    float a0 = INFINITY, a1 = INFINITY, a2 = INFINITY;
    float b0 = INFINITY, b1 = INFINITY, b2 = INFINITY;
    int   ia0 = 0, ia1 = 0, ia2 = 0;
    int   ib0 = 0, ib1 = 0, ib2 = 0;

    #pragma unroll 2
    for (int j = 0; j < CH; j += 4) {
        float4 p0 = sctx[j];
        float4 p1 = sctx[j + 1];
        float4 p2 = sctx[j + 2];
        float4 p3 = sctx[j + 3];

        // Bit-identical to the reference expansion: (|c|^2+|p|^2) - 2*dot
        float dA0 = (cnA + p0.w) - 2.0f * (qxA * p0.x + qyA * p0.y + qzA * p0.z);
        float dA1 = (cnA + p1.w) - 2.0f * (qxA * p1.x + qyA * p1.y + qzA * p1.z);
        float dA2 = (cnA + p2.w) - 2.0f * (qxA * p2.x + qyA * p2.y + qzA * p2.z);
        float dA3 = (cnA + p3.w) - 2.0f * (qxA * p3.x + qyA * p3.y + qzA * p3.z);

        float dB0 = (cnB + p0.w) - 2.0f * (qxB * p0.x + qyB * p0.y + qzB * p0.z);
        float dB1 = (cnB + p1.w) - 2.0f * (qxB * p1.x + qyB * p1.y + qzB * p1.z);
        float dB2 = (cnB + p2.w) - 2.0f * (qxB * p2.x + qyB * p2.y + qzB * p2.z);
        float dB3 = (cnB + p3.w) - 2.0f * (qxB * p3.x + qyB * p3.y + qzB * p3.z);

        float mA = fminf(fminf(dA0, dA1), fminf(dA2, dA3));
        float mB = fminf(fminf(dB0, dB1), fminf(dB2, dB3));

        if (mA < a2) {   // rare: ascending-j re-insert preserves exact tie order
            INS(a0, a1, a2, ia0, ia1, ia2, dA0, j0 + j);
            INS(a0, a1, a2, ia0, ia1, ia2, dA1, j0 + j + 1);
            INS(a0, a1, a2, ia0, ia1, ia2, dA2, j0 + j + 2);
            INS(a0, a1, a2, ia0, ia1, ia2, dA3, j0 + j + 3);
        }
        if (mB < b2) {
            INS(b0, b1, b2, ib0, ib1, ib2, dB0, j0 + j);
            INS(b0, b1, b2, ib0, ib1, ib2, dB1, j0 + j + 1);
            INS(b0, b1, b2, ib0, ib1, ib2, dB2, j0 + j + 2);
            INS(b0, b1, b2, ib0, ib1, ib2, dB3, j0 + j + 3);
        }
    }

    const int qA = b * NN + nA;
    const int qB_ = b * NN + nB;
    PD(0, s, qA) = a0;  PI(0, s, qA) = ia0;
    PD(1, s, qA) = a1;  PI(1, s, qA) = ia1;
    PD(2, s, qA) = a2;  PI(2, s, qA) = ia2;
    PD(0, s, qB_) = b0; PI(0, s, qB_) = ib0;
    PD(1, s, qB_) = b1; PI(1, s, qB_) = ib1;
    PD(2, s, qB_) = b2; PI(2, s, qB_) = ib2;
}

// Merge SPLIT partial triples per query (stable), then compute the epilogue.
__global__ void __launch_bounds__(256)
surf_merge_kernel(const float* __restrict__ context,
                  float* __restrict__ out)
{
    const int q = blockIdx.x * blockDim.x + threadIdx.x;
    if (q >= BB * NN) return;
    const int b = q / NN;
    const int n = q % NN;

    float d0 = INFINITY, d1 = INFINITY, d2 = INFINITY;
    int   i0 = 0, i1 = 0, i2 = 0;

    // Ascending split order + rank order -> exact global-scan tie semantics.
    #pragma unroll
    for (int s = 0; s < SPLIT; s++) {
        #pragma unroll
        for (int k = 0; k < 3; k++) {
            float d  = PD(k, s, q);
            int   jj = PI(k, s, q);
            INS(d0, d1, d2, i0, i1, i2, d, jj);
        }
    }

    const float* ctx = context + (size_t)b * 3 * MM;
    float g0x = ctx[i0], g0y = ctx[MM + i0], g0z = ctx[2 * MM + i0];
    float g1x = ctx[i1], g1y = ctx[MM + i1], g1z = ctx[2 * MM + i1];
    float g2x = ctx[i2], g2y = ctx[MM + i2], g2z = ctx[2 * MM + i2];

    float e1x = g1x - g0x, e1y = g1y - g0y, e1z = g1z - g0z;
    float e2x = g2x - g0x, e2y = g2y - g0y, e2z = g2z - g0z;

    float nx = e1y * e2z - e1z * e2y;
    float ny = e1z * e2x - e1x * e2z;
    float nz = e1x * e2y - e1y * e2x;

    float nrm = sqrtf(nx * nx + ny * ny + nz * nz);
    float ux = nx / nrm;
    float uy = ny / nrm;
    float uz = nz / nrm;

    float sg = (ux > 0.0f) ? 1.0f : -1.0f;   // NaN compares false -> -1
    ux *= sg; uy *= sg; uz *= sg;

    float cx = (g0x + g1x + g2x) / 3.0f;
    float cy = (g0y + g1y + g2y) / 3.0f;
    float cz = (g0z + g1z + g2z) / 3.0f;

    float pos = (ux * cx + uy * cy + uz * cz) / sqrtf(3.0f);

    bool bad = (ux != ux) || (uy != uy) || (uz != uz);
    g_mask[q] = bad ? 1 : 0;

    const size_t base = (size_t)b * 3 * NN + n;
    out[OFF_U + base]          = ux;
    out[OFF_U + base + NN]     = uy;
    out[OFF_U + base + 2 * NN] = uz;
    out[OFF_C + base]          = cx;
    out[OFF_C + base + NN]     = cy;
    out[OFF_C + base + 2 * NN] = cz;
    out[OFF_P + (size_t)b * NN + n] = pos;
}

// Per-batch first non-NaN row index (argmax(~mask): 0 if all masked)
__global__ void surf_first_kernel()
{
    const int b = blockIdx.x;
    __shared__ int sm;
    if (threadIdx.x == 0) sm = INT_MAX;
    __syncthreads();

    int m = INT_MAX;
    for (int n = threadIdx.x; n < NN; n += blockDim.x) {
        if (!g_mask[b * NN + n]) { m = n; break; }
    }
    atomicMin(&sm, m);
    __syncthreads();
    if (threadIdx.x == 0) g_first[b] = (sm == INT_MAX) ? 0 : sm;
}

// Rewrite masked rows with the first non-NaN row's values
__global__ void surf_fix_kernel(float* __restrict__ out)
{
    const int idx = blockIdx.x * blockDim.x + threadIdx.x;
    if (idx >= BB * NN) return;
    if (!g_mask[idx]) return;

    const int b = idx / NN;
    const int n = idx % NN;
    const int f = g_first[b];

    const size_t src = (size_t)b * 3 * NN + f;
    const size_t dst = (size_t)b * 3 * NN + n;

    out[OFF_U + dst]          = out[OFF_U + src];
    out[OFF_U + dst + NN]     = out[OFF_U + src + NN];
    out[OFF_U + dst + 2 * NN] = out[OFF_U + src + 2 * NN];
    out[OFF_C + dst]          = out[OFF_C + src];
    out[OFF_C + dst + NN]     = out[OFF_C + src + NN];
    out[OFF_C + dst + 2 * NN] = out[OFF_C + src + 2 * NN];
    out[OFF_P + (size_t)b * NN + n] = out[OFF_P + (size_t)b * NN + f];
}

extern "C" void kernel_launch(void* const* d_in, const int* in_sizes, int n_in,
                              void* d_out, int out_size)
{
    const float* center  = (const float*)d_in[0];   // [B,3,N]
    const float* context = (const float*)d_in[1];   // [B,3,M]
    float* out = (float*)d_out;

    surf_scan_kernel<<<BB * QB * SPLIT, TPB>>>(center, context);
    surf_merge_kernel<<<(BB * NN + 255) / 256, 256>>>(context, out);
    surf_first_kernel<<<BB, 256>>>();
    surf_fix_kernel<<<(BB * NN + 255) / 256, 256>>>(out);
}

// round 4
// speedup vs baseline: 1.2036x; 1.2036x over previous
#include <cuda_runtime.h>
#include <math.h>
#include <limits.h>

// Problem constants (fixed by the reference setup_inputs)
#define BB    4
#define NN    8192
#define MM    8192
#define TPB   256
#define SPLIT 8
#define CH    (MM / SPLIT)            // 1024 context points per chunk
#define BPB   (NN / TPB)              // 32 query-blocks per batch

// Output layout: [unit BB*3*NN][cen BB*3*NN][pos BB*NN]
#define OFF_U 0
#define OFF_C (BB * 3 * NN)
#define OFF_P (2 * BB * 3 * NN)

// Scratch (allocation-free: __device__ globals)
__device__ float g_pd[3 * SPLIT * BB * NN];
__device__ int   g_pi[3 * SPLIT * BB * NN];
__device__ unsigned char g_mask[BB * NN];
__device__ int g_first[BB];

#define PD(k, s, q) g_pd[(((k) * SPLIT + (s)) * (BB * NN)) + (q)]
#define PI(k, s, q) g_pi[(((k) * SPLIT + (s)) * (BB * NN)) + (q)]

// Stable top-3 insert (strict '<' => lowest-index-first ties, matches lax.top_k)
#define INS(d, jj)                                                           \
    if ((d) < d2) {                                                          \
        if ((d) < d0)      { d2 = d1; i2 = i1; d1 = d0; i1 = i0;             \
                             d0 = (d); i0 = (jj); }                          \
        else if ((d) < d1) { d2 = d1; i2 = i1; d1 = (d); i1 = (jj); }        \
        else               { d2 = (d); i2 = (jj); }                          \
    }

__global__ void __launch_bounds__(TPB)
surf_scan_kernel(const float* __restrict__ center,
                 const float* __restrict__ context)
{
    __shared__ float4 sctx[CH];   // 16 KB

    // blockIdx.x = ((b * BPB) + qb) * SPLIT + s
    const int s  = blockIdx.x % SPLIT;
    const int r  = blockIdx.x / SPLIT;
    const int qb = r % BPB;
    const int b  = r / BPB;
    const int j0 = s * CH;

    // Cooperative load of this chunk as (x, y, z, |p|^2)
    const float* ctx = context + (size_t)b * 3 * MM;
    #pragma unroll
    for (int j = threadIdx.x; j < CH; j += TPB) {
        float x = ctx[j0 + j];
        float y = ctx[MM + j0 + j];
        float z = ctx[2 * MM + j0 + j];
        sctx[j] = make_float4(x, y, z, x * x + y * y + z * z);
    }
    __syncthreads();

    // This thread's query point
    const int n = qb * TPB + threadIdx.x;
    const float* cenp = center + (size_t)b * 3 * NN;
    const float qx = cenp[n];
    const float qy = cenp[NN + n];
    const float qz = cenp[2 * NN + n];
    const float cn = qx * qx + qy * qy + qz * qz;

    float d0 = INFINITY, d1 = INFINITY, d2 = INFINITY;
    int   i0 = 0, i1 = 0, i2 = 0;

    // Group-of-4: 4 independent distance chains, one rare branch per group.
    #pragma unroll 4
    for (int j = 0; j < CH; j += 4) {
        float4 p0 = sctx[j];
        float4 p1 = sctx[j + 1];
        float4 p2 = sctx[j + 2];
        float4 p3 = sctx[j + 3];

        // Bit-identical to the reference expansion: (|c|^2+|p|^2) - 2*dot
        float da = (cn + p0.w) - 2.0f * (qx * p0.x + qy * p0.y + qz * p0.z);
        float db = (cn + p1.w) - 2.0f * (qx * p1.x + qy * p1.y + qz * p1.z);
        float dc = (cn + p2.w) - 2.0f * (qx * p2.x + qy * p2.y + qz * p2.z);
        float dd = (cn + p3.w) - 2.0f * (qx * p3.x + qy * p3.y + qz * p3.z);

        float m = fminf(fminf(da, db), fminf(dc, dd));
        if (m < d2) {   // rare: ascending-j re-insert preserves exact tie order
            INS(da, j0 + j);
            INS(db, j0 + j + 1);
            INS(dc, j0 + j + 2);
            INS(dd, j0 + j + 3);
        }
    }

    const int q = b * NN + n;
    PD(0, s, q) = d0;  PI(0, s, q) = i0;
    PD(1, s, q) = d1;  PI(1, s, q) = i1;
    PD(2, s, q) = d2;  PI(2, s, q) = i2;
}

// Merge SPLIT partial triples per query (stable), then compute the epilogue.
__global__ void __launch_bounds__(256)
surf_merge_kernel(const float* __restrict__ context,
                  float* __restrict__ out)
{
    const int q = blockIdx.x * blockDim.x + threadIdx.x;
    if (q >= BB * NN) return;
    const int b = q / NN;
    const int n = q % NN;

    float d0 = INFINITY, d1 = INFINITY, d2 = INFINITY;
    int   i0 = 0, i1 = 0, i2 = 0;

    // Ascending split order + rank order -> exact global-scan tie semantics.
    #pragma unroll
    for (int s = 0; s < SPLIT; s++) {
        #pragma unroll
        for (int k = 0; k < 3; k++) {
            float d  = PD(k, s, q);
            int   jj = PI(k, s, q);
            INS(d, jj);
        }
    }

    const float* ctx = context + (size_t)b * 3 * MM;
    float g0x = ctx[i0], g0y = ctx[MM + i0], g0z = ctx[2 * MM + i0];
    float g1x = ctx[i1], g1y = ctx[MM + i1], g1z = ctx[2 * MM + i1];
    float g2x = ctx[i2], g2y = ctx[MM + i2], g2z = ctx[2 * MM + i2];

    float e1x = g1x - g0x, e1y = g1y - g0y, e1z = g1z - g0z;
    float e2x = g2x - g0x, e2y = g2y - g0y, e2z = g2z - g0z;

    float nx = e1y * e2z - e1z * e2y;
    float ny = e1z * e2x - e1x * e2z;
    float nz = e1x * e2y - e1y * e2x;

    float nrm = sqrtf(nx * nx + ny * ny + nz * nz);
    float ux = nx / nrm;
    float uy = ny / nrm;
    float uz = nz / nrm;

    float sg = (ux > 0.0f) ? 1.0f : -1.0f;   // NaN compares false -> -1
    ux *= sg; uy *= sg; uz *= sg;

    float cx = (g0x + g1x + g2x) / 3.0f;
    float cy = (g0y + g1y + g2y) / 3.0f;
    float cz = (g0z + g1z + g2z) / 3.0f;

    float pos = (ux * cx + uy * cy + uz * cz) / sqrtf(3.0f);

    bool bad = (ux != ux) || (uy != uy) || (uz != uz);
    g_mask[q] = bad ? 1 : 0;

    const size_t base = (size_t)b * 3 * NN + n;
    out[OFF_U + base]          = ux;
    out[OFF_U + base + NN]     = uy;
    out[OFF_U + base + 2 * NN] = uz;
    out[OFF_C + base]          = cx;
    out[OFF_C + base + NN]     = cy;
    out[OFF_C + base + 2 * NN] = cz;
    out[OFF_P + (size_t)b * NN + n] = pos;
}

// Per-batch first non-NaN row index (argmax(~mask): 0 if all masked)
__global__ void surf_first_kernel()
{
    const int b = blockIdx.x;
    __shared__ int sm;
    if (threadIdx.x == 0) sm = INT_MAX;
    __syncthreads();

    int m = INT_MAX;
    for (int n = threadIdx.x; n < NN; n += blockDim.x) {
        if (!g_mask[b * NN + n]) { m = n; break; }
    }
    atomicMin(&sm, m);
    __syncthreads();
    if (threadIdx.x == 0) g_first[b] = (sm == INT_MAX) ? 0 : sm;
}

// Rewrite masked rows with the first non-NaN row's values
__global__ void surf_fix_kernel(float* __restrict__ out)
{
    const int idx = blockIdx.x * blockDim.x + threadIdx.x;
    if (idx >= BB * NN) return;
    if (!g_mask[idx]) return;

    const int b = idx / NN;
    const int n = idx % NN;
    const int f = g_first[b];

    const size_t src = (size_t)b * 3 * NN + f;
    const size_t dst = (size_t)b * 3 * NN + n;

    out[OFF_U + dst]          = out[OFF_U + src];
    out[OFF_U + dst + NN]     = out[OFF_U + src + NN];
    out[OFF_U + dst + 2 * NN] = out[OFF_U + src + 2 * NN];
    out[OFF_C + dst]          = out[OFF_C + src];
    out[OFF_C + dst + NN]     = out[OFF_C + src + NN];
    out[OFF_C + dst + 2 * NN] = out[OFF_C + src + 2 * NN];
    out[OFF_P + (size_t)b * NN + n] = out[OFF_P + (size_t)b * NN + f];
}

extern "C" void kernel_launch(void* const* d_in, const int* in_sizes, int n_in,
                              void* d_out, int out_size)
{
    const float* center  = (const float*)d_in[0];   // [B,3,N]
    const float* context = (const float*)d_in[1];   // [B,3,M]
    float* out = (float*)d_out;

    surf_scan_kernel<<<BB * BPB * SPLIT, TPB>>>(center, context);
    surf_merge_kernel<<<(BB * NN + 255) / 256, 256>>>(context, out);
    surf_first_kernel<<<BB, 256>>>();
    surf_fix_kernel<<<(BB * NN + 255) / 256, 256>>>(out);
}

// round 5
// speedup vs baseline: 1.5428x; 1.2818x over previous
#include <cuda_runtime.h>
#include <math.h>
#include <limits.h>

// Problem constants (fixed by the reference setup_inputs)
#define BB    4
#define NN    8192
#define MM    8192
#define TPB   256
#define SPLIT 4
#define CH    (MM / SPLIT)            // 2048 context points per chunk
#define BPB   (NN / TPB)              // 32 query-blocks per batch

// Output layout: [unit BB*3*NN][cen BB*3*NN][pos BB*NN]
#define OFF_U 0
#define OFF_C (BB * 3 * NN)
#define OFF_P (2 * BB * 3 * NN)

// Scratch (allocation-free: __device__ globals)
__device__ float g_pd[3 * SPLIT * BB * NN];
__device__ int   g_pi[3 * SPLIT * BB * NN];
__device__ unsigned char g_mask[BB * NN];
__device__ int g_first[BB];

#define PD(k, s, q) g_pd[(((k) * SPLIT + (s)) * (BB * NN)) + (q)]
#define PI(k, s, q) g_pi[(((k) * SPLIT + (s)) * (BB * NN)) + (q)]

// ---- packed f32x2 helpers (Blackwell sm_100+) ----
typedef unsigned long long u64;

__device__ __forceinline__ u64 f2pk(float lo, float hi) {
    u64 r;
    asm("mov.b64 %0, {%1, %2};" : "=l"(r)
        : "r"(__float_as_uint(lo)), "r"(__float_as_uint(hi)));
    return r;
}
__device__ __forceinline__ void f2un(u64 v, float& lo, float& hi) {
    unsigned a, b;
    asm("mov.b64 {%0, %1}, %2;" : "=r"(a), "=r"(b) : "l"(v));
    lo = __uint_as_float(a); hi = __uint_as_float(b);
}
__device__ __forceinline__ u64 mul2(u64 a, u64 b) {
    u64 r; asm("mul.rn.f32x2 %0, %1, %2;" : "=l"(r) : "l"(a), "l"(b)); return r;
}
__device__ __forceinline__ u64 add2(u64 a, u64 b) {
    u64 r; asm("add.rn.f32x2 %0, %1, %2;" : "=l"(r) : "l"(a), "l"(b)); return r;
}
__device__ __forceinline__ u64 fma2(u64 a, u64 b, u64 c) {
    u64 r; asm("fma.rn.f32x2 %0, %1, %2, %3;" : "=l"(r) : "l"(a), "l"(b), "l"(c)); return r;
}

// Branchless stable top-3 insert (FSETP+SEL, no BSSY/BSYNC). Strict '<' keeps
// the earlier-inserted entry on exact ties => must be applied in ascending-j
// order, matching lax.top_k. Semantically identical to the nested-if version.
#define INSB(d, jj) {                                                        \
    bool lt2 = (d) < d2, lt1 = (d) < d1, lt0 = (d) < d0;                     \
    float nd2 = lt1 ? d1 : (d);  int ni2 = lt1 ? i1 : (jj);                  \
    float nd1 = lt0 ? d0 : (d);  int ni1 = lt0 ? i0 : (jj);                  \
    d2 = lt2 ? nd2 : d2;  i2 = lt2 ? ni2 : i2;                               \
    d1 = lt1 ? nd1 : d1;  i1 = lt1 ? ni1 : i1;                               \
    d0 = lt0 ? (d) : d0;  i0 = lt0 ? (jj) : i0;                              \
}

__global__ void __launch_bounds__(TPB)
surf_scan_kernel(const float* __restrict__ center,
                 const float* __restrict__ context)
{
    // Pair-interleaved context: sA[p]={x0,x1,y0,y1}, sB[p]={z0,z1,w0,w1}
    __shared__ float4 sA[CH / 2];   // 16 KB
    __shared__ float4 sB[CH / 2];   // 16 KB

    // One-time scratch init for this replay (merge runs after scan completes)
    if (blockIdx.x < BB && threadIdx.x == 0) g_first[blockIdx.x] = INT_MAX;

    // blockIdx.x = ((b * BPB) + qb) * SPLIT + s
    const int s  = blockIdx.x % SPLIT;
    const int r  = blockIdx.x / SPLIT;
    const int qb = r % BPB;
    const int b  = r / BPB;
    const int j0 = s * CH;

    const float* ctx = context + (size_t)b * 3 * MM;
    for (int j = threadIdx.x; j < CH; j += TPB) {
        float x = ctx[j0 + j];
        float y = ctx[MM + j0 + j];
        float z = ctx[2 * MM + j0 + j];
        float w = x * x + y * y + z * z;
        int p = j >> 1, l = j & 1;
        float* a  = (float*)&sA[p];
        float* bp = (float*)&sB[p];
        a[l] = x;  a[2 + l] = y;
        bp[l] = z; bp[2 + l] = w;
    }
    __syncthreads();

    // This thread's query point
    const int n = qb * TPB + threadIdx.x;
    const float* cenp = center + (size_t)b * 3 * NN;
    const float qx = cenp[n];
    const float qy = cenp[NN + n];
    const float qz = cenp[2 * NN + n];
    const float cn = qx * qx + qy * qy + qz * qz;

    const u64 QX2  = f2pk(qx, qx);
    const u64 QY2  = f2pk(qy, qy);
    const u64 QZ2  = f2pk(qz, qz);
    const u64 CN2  = f2pk(cn, cn);
    const u64 NEG2 = f2pk(-2.0f, -2.0f);

    float d0 = INFINITY, d1 = INFINITY, d2 = INFINITY;
    int   i0 = 0, i1 = 0, i2 = 0;

    #pragma unroll 2
    for (int p = 0; p < CH / 2; p += 2) {     // 4 points per iteration
        float4 A0 = sA[p],     B0 = sB[p];
        float4 A1 = sA[p + 1], B1 = sB[p + 1];

        // d = (cn + |p|^2) - 2*dot, two points per packed op
        u64 t0 = mul2(QX2, f2pk(A0.x, A0.y));
        t0 = fma2(QY2, f2pk(A0.z, A0.w), t0);
        t0 = fma2(QZ2, f2pk(B0.x, B0.y), t0);
        u64 dp0 = fma2(NEG2, t0, add2(CN2, f2pk(B0.z, B0.w)));

        u64 t1 = mul2(QX2, f2pk(A1.x, A1.y));
        t1 = fma2(QY2, f2pk(A1.z, A1.w), t1);
        t1 = fma2(QZ2, f2pk(B1.x, B1.y), t1);
        u64 dp1 = fma2(NEG2, t1, add2(CN2, f2pk(B1.z, B1.w)));

        float da, db, dc, dd;
        f2un(dp0, da, db);
        f2un(dp1, dc, dd);

        float m = fminf(fminf(da, db), fminf(dc, dd));
        if (m < d2) {                         // rare for large j
            const int jj = j0 + 2 * p;
            bool pa = da < d2, pb = db < d2, pc = dc < d2, pd = dd < d2;
            int cnt = (int)pa + (int)pb + (int)pc + (int)pd;
            if (cnt == 1) {
                // exactly one candidate: order-independent single insert
                float ds = pa ? da : (pb ? db : (pc ? dc : dd));
                int   js = pa ? jj : (pb ? jj + 1 : (pc ? jj + 2 : jj + 3));
                INSB(ds, js);
            } else {
                // ascending-j sequential inserts: exact tie semantics
                INSB(da, jj);
                INSB(db, jj + 1);
                INSB(dc, jj + 2);
                INSB(dd, jj + 3);
            }
        }
    }

    const int q = b * NN + n;
    PD(0, s, q) = d0;  PI(0, s, q) = i0;
    PD(1, s, q) = d1;  PI(1, s, q) = i1;
    PD(2, s, q) = d2;  PI(2, s, q) = i2;
}

// Merge SPLIT partial triples per query, epilogue, mask, first-good-row.
__global__ void __launch_bounds__(256)
surf_merge_kernel(const float* __restrict__ context,
                  float* __restrict__ out)
{
    const int q = blockIdx.x * blockDim.x + threadIdx.x;
    if (q >= BB * NN) return;
    const int b = q / NN;
    const int n = q % NN;

    float d0 = INFINITY, d1 = INFINITY, d2 = INFINITY;
    int   i0 = 0, i1 = 0, i2 = 0;

    // Ascending split order + rank order -> exact global-scan tie semantics.
    #pragma unroll
    for (int s = 0; s < SPLIT; s++) {
        #pragma unroll
        for (int k = 0; k < 3; k++) {
            float d  = PD(k, s, q);
            int   jj = PI(k, s, q);
            INSB(d, jj);
        }
    }

    const float* ctx = context + (size_t)b * 3 * MM;
    float g0x = ctx[i0], g0y = ctx[MM + i0], g0z = ctx[2 * MM + i0];
    float g1x = ctx[i1], g1y = ctx[MM + i1], g1z = ctx[2 * MM + i1];
    float g2x = ctx[i2], g2y = ctx[MM + i2], g2z = ctx[2 * MM + i2];

    float e1x = g1x - g0x, e1y = g1y - g0y, e1z = g1z - g0z;
    float e2x = g2x - g0x, e2y = g2y - g0y, e2z = g2z - g0z;

    float nx = e1y * e2z - e1z * e2y;
    float ny = e1z * e2x - e1x * e2z;
    float nz = e1x * e2y - e1y * e2x;

    float nrm = sqrtf(nx * nx + ny * ny + nz * nz);
    float ux = nx / nrm;
    float uy = ny / nrm;
    float uz = nz / nrm;

    float sg = (ux > 0.0f) ? 1.0f : -1.0f;   // NaN compares false -> -1
    ux *= sg; uy *= sg; uz *= sg;

    float cx = (g0x + g1x + g2x) / 3.0f;
    float cy = (g0y + g1y + g2y) / 3.0f;
    float cz = (g0z + g1z + g2z) / 3.0f;

    float pos = (ux * cx + uy * cy + uz * cz) / sqrtf(3.0f);

    bool bad = (ux != ux) || (uy != uy) || (uz != uz);
    g_mask[q] = bad ? 1 : 0;

    // first non-NaN row per batch: warp-reduce then one atomic per warp.
    // Block is 256 threads over consecutive q of ONE batch slice (NN%256==0),
    // so all lanes share b.
    int v = bad ? INT_MAX : n;
    int wmin = __reduce_min_sync(0xffffffffu, v);
    if ((threadIdx.x & 31) == 0 && wmin != INT_MAX)
        atomicMin(&g_first[b], wmin);

    const size_t base = (size_t)b * 3 * NN + n;
    out[OFF_U + base]          = ux;
    out[OFF_U + base + NN]     = uy;
    out[OFF_U + base + 2 * NN] = uz;
    out[OFF_C + base]          = cx;
    out[OFF_C + base + NN]     = cy;
    out[OFF_C + base + 2 * NN] = cz;
    out[OFF_P + (size_t)b * NN + n] = pos;
}

// Rewrite masked rows with the first non-NaN row's values
__global__ void surf_fix_kernel(float* __restrict__ out)
{
    const int idx = blockIdx.x * blockDim.x + threadIdx.x;
    if (idx >= BB * NN) return;
    if (!g_mask[idx]) return;

    const int b = idx / NN;
    const int n = idx % NN;
    int f = g_first[b];
    if (f == INT_MAX) f = 0;   // all-masked: reference argmax(~mask) = 0

    const size_t src = (size_t)b * 3 * NN + f;
    const size_t dst = (size_t)b * 3 * NN + n;

    out[OFF_U + dst]          = out[OFF_U + src];
    out[OFF_U + dst + NN]     = out[OFF_U + src + NN];
    out[OFF_U + dst + 2 * NN] = out[OFF_U + src + 2 * NN];
    out[OFF_C + dst]          = out[OFF_C + src];
    out[OFF_C + dst + NN]     = out[OFF_C + src + NN];
    out[OFF_C + dst + 2 * NN] = out[OFF_C + src + 2 * NN];
    out[OFF_P + (size_t)b * NN + n] = out[OFF_P + (size_t)b * NN + f];
}

extern "C" void kernel_launch(void* const* d_in, const int* in_sizes, int n_in,
                              void* d_out, int out_size)
{
    const float* center  = (const float*)d_in[0];   // [B,3,N]
    const float* context = (const float*)d_in[1];   // [B,3,M]
    float* out = (float*)d_out;

    surf_scan_kernel<<<BB * BPB * SPLIT, TPB>>>(center, context);
    surf_merge_kernel<<<(BB * NN + 255) / 256, 256>>>(context, out);
    surf_fix_kernel<<<(BB * NN + 255) / 256, 256>>>(out);
}

// round 7
// speedup vs baseline: 1.6138x; 1.0461x over previous
#include <cuda_runtime.h>
#include <math.h>
#include <limits.h>

// Problem constants (fixed by the reference setup_inputs)
#define BB    4
#define NN    8192
#define MM    8192
#define TPB   256
#define SPLIT 8
#define CH    (MM / SPLIT)            // 1024 context points per chunk
#define BPB   (NN / TPB)              // 32 query-blocks per batch

// Output layout: [unit BB*3*NN][cen BB*3*NN][pos BB*NN]
#define OFF_U 0
#define OFF_C (BB * 3 * NN)
#define OFF_P (2 * BB * 3 * NN)

// Scratch (allocation-free: __device__ globals)
__device__ float g_pd[3 * SPLIT * BB * NN];
__device__ int   g_pi[3 * SPLIT * BB * NN];
__device__ unsigned char g_mask[BB * NN];
__device__ int g_first[BB];

#define PD(k, s, q) g_pd[(((k) * SPLIT + (s)) * (BB * NN)) + (q)]
#define PI(k, s, q) g_pi[(((k) * SPLIT + (s)) * (BB * NN)) + (q)]

// ---- packed f32x2 helpers (Blackwell sm_100+) ----
typedef unsigned long long u64;

__device__ __forceinline__ u64 f2pk(float lo, float hi) {
    u64 r;
    asm("mov.b64 %0, {%1, %2};" : "=l"(r)
        : "r"(__float_as_uint(lo)), "r"(__float_as_uint(hi)));
    return r;
}
__device__ __forceinline__ void f2un(u64 v, float& lo, float& hi) {
    unsigned a, b;
    asm("mov.b64 {%0, %1}, %2;" : "=r"(a), "=r"(b) : "l"(v));
    lo = __uint_as_float(a); hi = __uint_as_float(b);
}
__device__ __forceinline__ u64 mul2(u64 a, u64 b) {
    u64 r; asm("mul.rn.f32x2 %0, %1, %2;" : "=l"(r) : "l"(a), "l"(b)); return r;
}
__device__ __forceinline__ u64 add2(u64 a, u64 b) {
    u64 r; asm("add.rn.f32x2 %0, %1, %2;" : "=l"(r) : "l"(a), "l"(b)); return r;
}
__device__ __forceinline__ u64 fma2(u64 a, u64 b, u64 c) {
    u64 r; asm("fma.rn.f32x2 %0, %1, %2, %3;" : "=l"(r) : "l"(a), "l"(b), "l"(c)); return r;
}

// Branchless stable top-3 insert (FSETP+SEL). Strict '<' keeps the
// earlier-inserted entry on exact ties => apply in ascending-j order,
// matching lax.top_k.
#define INSB(d, jj) {                                                        \
    bool lt2 = (d) < d2, lt1 = (d) < d1, lt0 = (d) < d0;                     \
    float nd2 = lt1 ? d1 : (d);  int ni2 = lt1 ? i1 : (jj);                  \
    float nd1 = lt0 ? d0 : (d);  int ni1 = lt0 ? i0 : (jj);                  \
    d2 = lt2 ? nd2 : d2;  i2 = lt2 ? ni2 : i2;                               \
    d1 = lt1 ? nd1 : d1;  i1 = lt1 ? ni1 : i1;                               \
    d0 = lt0 ? (d) : d0;  i0 = lt0 ? (jj) : i0;                              \
}

__global__ void __launch_bounds__(TPB)
surf_scan_kernel(const float* __restrict__ center,
                 const float* __restrict__ context)
{
    // Context pre-packed as f32x2 pairs: sXY[p]={(x0,x1),(y0,y1)},
    // sZW[p]={(z0,z1),(w0,w1)}. LDS.128 lands packed operands directly in
    // 64-bit register pairs -> no marshalling movs in the hot loop.
    __shared__ __align__(16) ulonglong2 sXY[CH / 2];   // 8 KB
    __shared__ __align__(16) ulonglong2 sZW[CH / 2];   // 8 KB

    // One-time scratch init for this replay (merge runs after scan completes)
    if (blockIdx.x < BB && threadIdx.x == 0) g_first[blockIdx.x] = INT_MAX;

    // blockIdx.x = ((b * BPB) + qb) * SPLIT + s
    const int s  = blockIdx.x % SPLIT;
    const int r  = blockIdx.x / SPLIT;
    const int qb = r % BPB;
    const int b  = r / BPB;
    const int j0 = s * CH;

    // Load phase: each thread handles an even/odd point pair lane, writing
    // f32x2-packed words at 8-byte granularity.
    const float* ctx = context + (size_t)b * 3 * MM;
    for (int j = threadIdx.x; j < CH; j += TPB) {
        float x = ctx[j0 + j];
        float y = ctx[MM + j0 + j];
        float z = ctx[2 * MM + j0 + j];
        float w = x * x + y * y + z * z;
        const int p = j >> 1, l = j & 1;
        float* fxy = (float*)&sXY[p];
        float* fzw = (float*)&sZW[p];
        fxy[l]     = x;   // (x0,x1) lives in fxy[0..1]
        fxy[2 + l] = y;   // (y0,y1) in fxy[2..3]
        fzw[l]     = z;   // (z0,z1)
        fzw[2 + l] = w;   // (w0,w1)
    }
    __syncthreads();

    // This thread's query point
    const int n = qb * TPB + threadIdx.x;
    const float* cenp = center + (size_t)b * 3 * NN;
    const float qx = cenp[n];
    const float qy = cenp[NN + n];
    const float qz = cenp[2 * NN + n];
    const float cn = qx * qx + qy * qy + qz * qz;

    const u64 QX2  = f2pk(qx, qx);
    const u64 QY2  = f2pk(qy, qy);
    const u64 QZ2  = f2pk(qz, qz);
    const u64 CN2  = f2pk(cn, cn);
    const u64 NEG2 = f2pk(-2.0f, -2.0f);

    float d0 = INFINITY, d1 = INFINITY, d2 = INFINITY;
    int   i0 = 0, i1 = 0, i2 = 0;

    #pragma unroll 4
    for (int p = 0; p < CH / 2; p += 2) {     // 4 points per iteration
        ulonglong2 v0 = sXY[p];               // {x0x1, y0y1}
        ulonglong2 w0 = sZW[p];               // {z0z1, w0w1}
        ulonglong2 v1 = sXY[p + 1];
        ulonglong2 w1 = sZW[p + 1];

        // d = (cn + |p|^2) - 2*dot, two points per packed op
        u64 t0 = mul2(QX2, v0.x);
        t0 = fma2(QY2, v0.y, t0);
        t0 = fma2(QZ2, w0.x, t0);
        u64 dp0 = fma2(NEG2, t0, add2(CN2, w0.y));

        u64 t1 = mul2(QX2, v1.x);
        t1 = fma2(QY2, v1.y, t1);
        t1 = fma2(QZ2, w1.x, t1);
        u64 dp1 = fma2(NEG2, t1, add2(CN2, w1.y));

        float da, db, dc, dd;
        f2un(dp0, da, db);
        f2un(dp1, dc, dd);

        float m = fminf(fminf(da, db), fminf(dc, dd));
        if (m < d2) {                         // rare (~5% of groups)
            const int jj = j0 + 2 * p;
            bool pa = da < d2, pb = db < d2, pc = dc < d2, pd = dd < d2;
            int cnt = (int)pa + (int)pb + (int)pc + (int)pd;
            if (cnt == 1) {
                // exactly one candidate: order-independent single insert
                float ds = pa ? da : (pb ? db : (pc ? dc : dd));
                int   js = pa ? jj : (pb ? jj + 1 : (pc ? jj + 2 : jj + 3));
                INSB(ds, js);
            } else {
                // ascending-j sequential inserts: exact tie semantics
                INSB(da, jj);
                INSB(db, jj + 1);
                INSB(dc, jj + 2);
                INSB(dd, jj + 3);
            }
        }
    }

    const int q = b * NN + n;
    PD(0, s, q) = d0;  PI(0, s, q) = i0;
    PD(1, s, q) = d1;  PI(1, s, q) = i1;
    PD(2, s, q) = d2;  PI(2, s, q) = i2;
}

// Merge SPLIT partial triples per query, epilogue, mask, first-good-row.
__global__ void __launch_bounds__(256)
surf_merge_kernel(const float* __restrict__ context,
                  float* __restrict__ out)
{
    const int q = blockIdx.x * blockDim.x + threadIdx.x;
    if (q >= BB * NN) return;
    const int b = q / NN;
    const int n = q % NN;

    float d0 = INFINITY, d1 = INFINITY, d2 = INFINITY;
    int   i0 = 0, i1 = 0, i2 = 0;

    // Ascending split order + rank order -> exact global-scan tie semantics.
    #pragma unroll
    for (int s = 0; s < SPLIT; s++) {
        #pragma unroll
        for (int k = 0; k < 3; k++) {
            float d  = PD(k, s, q);
            int   jj = PI(k, s, q);
            INSB(d, jj);
        }
    }

    const float* ctx = context + (size_t)b * 3 * MM;
    float g0x = ctx[i0], g0y = ctx[MM + i0], g0z = ctx[2 * MM + i0];
    float g1x = ctx[i1], g1y = ctx[MM + i1], g1z = ctx[2 * MM + i1];
    float g2x = ctx[i2], g2y = ctx[MM + i2], g2z = ctx[2 * MM + i2];

    float e1x = g1x - g0x, e1y = g1y - g0y, e1z = g1z - g0z;
    float e2x = g2x - g0x, e2y = g2y - g0y, e2z = g2z - g0z;

    float nx = e1y * e2z - e1z * e2y;
    float ny = e1z * e2x - e1x * e2z;
    float nz = e1x * e2y - e1y * e2x;

    float nrm = sqrtf(nx * nx + ny * ny + nz * nz);
    float ux = nx / nrm;
    float uy = ny / nrm;
    float uz = nz / nrm;

    float sg = (ux > 0.0f) ? 1.0f : -1.0f;   // NaN compares false -> -1
    ux *= sg; uy *= sg; uz *= sg;

    float cx = (g0x + g1x + g2x) / 3.0f;
    float cy = (g0y + g1y + g2y) / 3.0f;
    float cz = (g0z + g1z + g2z) / 3.0f;

    float pos = (ux * cx + uy * cy + uz * cz) / sqrtf(3.0f);

    bool bad = (ux != ux) || (uy != uy) || (uz != uz);
    g_mask[q] = bad ? 1 : 0;

    // first non-NaN row per batch: warp-reduce then one atomic per warp.
    // Block covers consecutive q within ONE batch (NN % 256 == 0).
    int v = bad ? INT_MAX : n;
    int wmin = __reduce_min_sync(0xffffffffu, v);
    if ((threadIdx.x & 31) == 0 && wmin != INT_MAX)
        atomicMin(&g_first[b], wmin);

    const size_t base = (size_t)b * 3 * NN + n;
    out[OFF_U + base]          = ux;
    out[OFF_U + base + NN]     = uy;
    out[OFF_U + base + 2 * NN] = uz;
    out[OFF_C + base]          = cx;
    out[OFF_C + base + NN]     = cy;
    out[OFF_C + base + 2 * NN] = cz;
    out[OFF_P + (size_t)b * NN + n] = pos;
}

// Rewrite masked rows with the first non-NaN row's values
__global__ void surf_fix_kernel(float* __restrict__ out)
{
    const int idx = blockIdx.x * blockDim.x + threadIdx.x;
    if (idx >= BB * NN) return;
    if (!g_mask[idx]) return;

    const int b = idx / NN;
    const int n = idx % NN;
    int f = g_first[b];
    if (f == INT_MAX) f = 0;   // all-masked: reference argmax(~mask) = 0

    const size_t src = (size_t)b * 3 * NN + f;
    const size_t dst = (size_t)b * 3 * NN + n;

    out[OFF_U + dst]          = out[OFF_U + src];
    out[OFF_U + dst + NN]     = out[OFF_U + src + NN];
    out[OFF_U + dst + 2 * NN] = out[OFF_U + src + 2 * NN];
    out[OFF_C + dst]          = out[OFF_C + src];
    out[OFF_C + dst + NN]     = out[OFF_C + src + NN];
    out[OFF_C + dst + 2 * NN] = out[OFF_C + src + 2 * NN];
    out[OFF_P + (size_t)b * NN + n] = out[OFF_P + (size_t)b * NN + f];
}

extern "C" void kernel_launch(void* const* d_in, const int* in_sizes, int n_in,
                              void* d_out, int out_size)
{
    const float* center  = (const float*)d_in[0];   // [B,3,N]
    const float* context = (const float*)d_in[1];   // [B,3,M]
    float* out = (float*)d_out;

    surf_scan_kernel<<<BB * BPB * SPLIT, TPB>>>(center, context);
    surf_merge_kernel<<<(BB * NN + 255) / 256, 256>>>(context, out);
    surf_fix_kernel<<<(BB * NN + 255) / 256, 256>>>(out);
}

// round 9
// speedup vs baseline: 1.6326x; 1.0116x over previous
#include <cuda_runtime.h>
#include <math.h>
#include <limits.h>

// Problem constants (fixed by the reference setup_inputs)
#define BB    4
#define NN    8192
#define MM    8192
#define TPB   256
#define SPLIT 8
#define CH    (MM / SPLIT)            // 1024 context points per chunk
#define BPB   (NN / TPB)              // 32 query-blocks per batch

// Output layout: [unit BB*3*NN][cen BB*3*NN][pos BB*NN]
#define OFF_U 0
#define OFF_C (BB * 3 * NN)
#define OFF_P (2 * BB * 3 * NN)

// Scratch (allocation-free: __device__ globals)
__device__ float g_pd[3 * SPLIT * BB * NN];
__device__ int   g_pi[3 * SPLIT * BB * NN];
__device__ unsigned char g_mask[BB * NN];
__device__ int g_first[BB];

#define PD(k, s, q) g_pd[(((k) * SPLIT + (s)) * (BB * NN)) + (q)]
#define PI(k, s, q) g_pi[(((k) * SPLIT + (s)) * (BB * NN)) + (q)]

// ---- packed f32x2 helpers (Blackwell sm_100+): mul/add/fma only ----
typedef unsigned long long u64;

__device__ __forceinline__ u64 f2pk(float lo, float hi) {
    u64 r;
    asm("mov.b64 %0, {%1, %2};" : "=l"(r)
        : "r"(__float_as_uint(lo)), "r"(__float_as_uint(hi)));
    return r;
}
__device__ __forceinline__ void f2un(u64 v, float& lo, float& hi) {
    unsigned a, b;
    asm("mov.b64 {%0, %1}, %2;" : "=r"(a), "=r"(b) : "l"(v));
    lo = __uint_as_float(a); hi = __uint_as_float(b);
}
__device__ __forceinline__ u64 mul2(u64 a, u64 b) {
    u64 r; asm("mul.rn.f32x2 %0, %1, %2;" : "=l"(r) : "l"(a), "l"(b)); return r;
}
__device__ __forceinline__ u64 add2(u64 a, u64 b) {
    u64 r; asm("add.rn.f32x2 %0, %1, %2;" : "=l"(r) : "l"(a), "l"(b)); return r;
}
__device__ __forceinline__ u64 fma2(u64 a, u64 b, u64 c) {
    u64 r; asm("fma.rn.f32x2 %0, %1, %2, %3;" : "=l"(r) : "l"(a), "l"(b), "l"(c)); return r;
}

// Branchless stable top-3 insert (FSETP+SEL). Strict '<' keeps the
// earlier-inserted entry on exact ties => apply in ascending-j order,
// matching lax.top_k.
#define INSB(d, jj) {                                                        \
    bool lt2 = (d) < d2, lt1 = (d) < d1, lt0 = (d) < d0;                     \
    float nd2 = lt1 ? d1 : (d);  int ni2 = lt1 ? i1 : (jj);                  \
    float nd1 = lt0 ? d0 : (d);  int ni1 = lt0 ? i0 : (jj);                  \
    d2 = lt2 ? nd2 : d2;  i2 = lt2 ? ni2 : i2;                               \
    d1 = lt1 ? nd1 : d1;  i1 = lt1 ? ni1 : i1;                               \
    d0 = lt0 ? (d) : d0;  i0 = lt0 ? (jj) : i0;                              \
}

__global__ void __launch_bounds__(TPB)
surf_scan_kernel(const float* __restrict__ center,
                 const float* __restrict__ context)
{
    // Single interleaved packed layout: per point-pair p (points 2p, 2p+1),
    // sD[4p..4p+3] = { (x0,x1), (y0,y1), (z0,z1), (w0,w1) }  (32 bytes).
    // A 4-point group = 64 contiguous bytes -> 4x LDS.128 at immediate
    // offsets 0/16/32/48 from one base register.
    __shared__ __align__(16) u64 sD[(CH / 2) * 4];   // 16 KB

    // One-time scratch init for this replay (merge runs after scan completes)
    if (blockIdx.x < BB && threadIdx.x == 0) g_first[blockIdx.x] = INT_MAX;

    // blockIdx.x = ((b * BPB) + qb) * SPLIT + s
    const int s  = blockIdx.x % SPLIT;
    const int r  = blockIdx.x / SPLIT;
    const int qb = r % BPB;
    const int b  = r / BPB;
    const int j0 = s * CH;

    // Load phase: pack into interleaved f32x2 words (8-byte granular writes)
    const float* ctx = context + (size_t)b * 3 * MM;
    for (int j = threadIdx.x; j < CH; j += TPB) {
        float x = ctx[j0 + j];
        float y = ctx[MM + j0 + j];
        float z = ctx[2 * MM + j0 + j];
        float w = x * x + y * y + z * z;
        const int p = j >> 1, l = j & 1;
        float* f = (float*)&sD[4 * p];
        f[l]     = x;   // (x0,x1)
        f[2 + l] = y;   // (y0,y1)
        f[4 + l] = z;   // (z0,z1)
        f[6 + l] = w;   // (w0,w1)
    }
    __syncthreads();

    // This thread's query point
    const int n = qb * TPB + threadIdx.x;
    const float* cenp = center + (size_t)b * 3 * NN;
    const float qx = cenp[n];
    const float qy = cenp[NN + n];
    const float qz = cenp[2 * NN + n];
    const float cn = qx * qx + qy * qy + qz * qz;

    const u64 QX2  = f2pk(qx, qx);
    const u64 QY2  = f2pk(qy, qy);
    const u64 QZ2  = f2pk(qz, qz);
    const u64 CN2  = f2pk(cn, cn);
    const u64 NEG2 = f2pk(-2.0f, -2.0f);

    float d0 = INFINITY, d1 = INFINITY, d2 = INFINITY;
    int   i0 = 0, i1 = 0, i2 = 0;

    const ulonglong2* sV = (const ulonglong2*)sD;

    #pragma unroll 4
    for (int p = 0; p < CH / 2; p += 2) {     // 4 points per iteration
        ulonglong2 a0 = sV[2 * p];            // {x01, y01}
        ulonglong2 a1 = sV[2 * p + 1];        // {z01, w01}
        ulonglong2 a2 = sV[2 * p + 2];        // {x23, y23}
        ulonglong2 a3 = sV[2 * p + 3];        // {z23, w23}

        // d = (cn + |p|^2) - 2*dot — identical op sequence to prior rounds
        u64 t0 = mul2(QX2, a0.x);
        t0 = fma2(QY2, a0.y, t0);
        t0 = fma2(QZ2, a1.x, t0);
        u64 dp0 = fma2(NEG2, t0, add2(CN2, a1.y));

        u64 t1 = mul2(QX2, a2.x);
        t1 = fma2(QY2, a2.y, t1);
        t1 = fma2(QZ2, a3.x, t1);
        u64 dp1 = fma2(NEG2, t1, add2(CN2, a3.y));

        float da, db, dc, dd;
        f2un(dp0, da, db);
        f2un(dp1, dc, dd);

        float m = fminf(fminf(da, db), fminf(dc, dd));
        if (m < d2) {                         // rare (~5% of groups)
            const int jj = j0 + 2 * p;
            bool pa = da < d2, pb = db < d2, pc = dc < d2, pd = dd < d2;
            int cnt = (int)pa + (int)pb + (int)pc + (int)pd;
            if (cnt == 1) {
                // exactly one candidate: order-independent single insert
                float ds = pa ? da : (pb ? db : (pc ? dc : dd));
                int   js = pa ? jj : (pb ? jj + 1 : (pc ? jj + 2 : jj + 3));
                INSB(ds, js);
            } else {
                // ascending-j sequential inserts: exact tie semantics
                INSB(da, jj);
                INSB(db, jj + 1);
                INSB(dc, jj + 2);
                INSB(dd, jj + 3);
            }
        }
    }

    const int q = b * NN + n;
    PD(0, s, q) = d0;  PI(0, s, q) = i0;
    PD(1, s, q) = d1;  PI(1, s, q) = i1;
    PD(2, s, q) = d2;  PI(2, s, q) = i2;
}

// Merge SPLIT partial triples per query, epilogue, mask, first-good-row.
__global__ void __launch_bounds__(256)
surf_merge_kernel(const float* __restrict__ context,
                  float* __restrict__ out)
{
    const int q = blockIdx.x * blockDim.x + threadIdx.x;
    if (q >= BB * NN) return;
    const int b = q / NN;
    const int n = q % NN;

    float d0 = INFINITY, d1 = INFINITY, d2 = INFINITY;
    int   i0 = 0, i1 = 0, i2 = 0;

    // Ascending split order + rank order -> exact global-scan tie semantics.
    #pragma unroll
    for (int s = 0; s < SPLIT; s++) {
        #pragma unroll
        for (int k = 0; k < 3; k++) {
            float d  = PD(k, s, q);
            int   jj = PI(k, s, q);
            INSB(d, jj);
        }
    }

    const float* ctx = context + (size_t)b * 3 * MM;
    float g0x = ctx[i0], g0y = ctx[MM + i0], g0z = ctx[2 * MM + i0];
    float g1x = ctx[i1], g1y = ctx[MM + i1], g1z = ctx[2 * MM + i1];
    float g2x = ctx[i2], g2y = ctx[MM + i2], g2z = ctx[2 * MM + i2];

    float e1x = g1x - g0x, e1y = g1y - g0y, e1z = g1z - g0z;
    float e2x = g2x - g0x, e2y = g2y - g0y, e2z = g2z - g0z;

    float nx = e1y * e2z - e1z * e2y;
    float ny = e1z * e2x - e1x * e2z;
    float nz = e1x * e2y - e1y * e2x;

    float nrm = sqrtf(nx * nx + ny * ny + nz * nz);
    float ux = nx / nrm;
    float uy = ny / nrm;
    float uz = nz / nrm;

    float sg = (ux > 0.0f) ? 1.0f : -1.0f;   // NaN compares false -> -1
    ux *= sg; uy *= sg; uz *= sg;

    float cx = (g0x + g1x + g2x) / 3.0f;
    float cy = (g0y + g1y + g2y) / 3.0f;
    float cz = (g0z + g1z + g2z) / 3.0f;

    float pos = (ux * cx + uy * cy + uz * cz) / sqrtf(3.0f);

    bool bad = (ux != ux) || (uy != uy) || (uz != uz);
    g_mask[q] = bad ? 1 : 0;

    // first non-NaN row per batch: warp-reduce then one atomic per warp.
    // Block covers consecutive q within ONE batch (NN % 256 == 0).
    int v = bad ? INT_MAX : n;
    int wmin = __reduce_min_sync(0xffffffffu, v);
    if ((threadIdx.x & 31) == 0 && wmin != INT_MAX)
        atomicMin(&g_first[b], wmin);

    const size_t base = (size_t)b * 3 * NN + n;
    out[OFF_U + base]          = ux;
    out[OFF_U + base + NN]     = uy;
    out[OFF_U + base + 2 * NN] = uz;
    out[OFF_C + base]          = cx;
    out[OFF_C + base + NN]     = cy;
    out[OFF_C + base + 2 * NN] = cz;
    out[OFF_P + (size_t)b * NN + n] = pos;
}

// Rewrite masked rows with the first non-NaN row's values
__global__ void surf_fix_kernel(float* __restrict__ out)
{
    const int idx = blockIdx.x * blockDim.x + threadIdx.x;
    if (idx >= BB * NN) return;
    if (!g_mask[idx]) return;

    const int b = idx / NN;
    const int n = idx % NN;
    int f = g_first[b];
    if (f == INT_MAX) f = 0;   // all-masked: reference argmax(~mask) = 0

    const size_t src = (size_t)b * 3 * NN + f;
    const size_t dst = (size_t)b * 3 * NN + n;

    out[OFF_U + dst]          = out[OFF_U + src];
    out[OFF_U + dst + NN]     = out[OFF_U + src + NN];
    out[OFF_U + dst + 2 * NN] = out[OFF_U + src + 2 * NN];
    out[OFF_C + dst]          = out[OFF_C + src];
    out[OFF_C + dst + NN]     = out[OFF_C + src + NN];
    out[OFF_C + dst + 2 * NN] = out[OFF_C + src + 2 * NN];
    out[OFF_P + (size_t)b * NN + n] = out[OFF_P + (size_t)b * NN + f];
}

extern "C" void kernel_launch(void* const* d_in, const int* in_sizes, int n_in,
                              void* d_out, int out_size)
{
    const float* center  = (const float*)d_in[0];   // [B,3,N]
    const float* context = (const float*)d_in[1];   // [B,3,M]
    float* out = (float*)d_out;

    surf_scan_kernel<<<BB * BPB * SPLIT, TPB>>>(center, context);
    surf_merge_kernel<<<(BB * NN + 255) / 256, 256>>>(context, out);
    surf_fix_kernel<<<(BB * NN + 255) / 256, 256>>>(out);
}